// round 4
// baseline (speedup 1.0000x reference)
#include <cuda_runtime.h>
#include <math.h>

#define CH    96
#define HH    192
#define WWI   192
#define HW    (HH*WWI)        // 36864
#define BATCH 4
#define NWIN_PER 576          // 24*24 windows per image
#define NWIN  (BATCH*NWIN_PER)
#define NTOK  64
#define NHEAD 6
#define HDIM  16

// 56.6 MB each — static device scratch (no allocations allowed)
__device__ float g_imgA[BATCH*HW*CH];
__device__ float g_imgB[BATCH*HW*CH];

// ---------------------------------------------------------------------------
// FMA-only exp (avoids MUFU bottleneck: 113M exps would cost ~0.8ms on MUFU)
// Valid for x <= 0 (softmax-shifted logits); clamps at -80.
// ---------------------------------------------------------------------------
__device__ __forceinline__ float fexp(float x) {
    x = fmaxf(x, -80.0f);
    const float L2E = 1.4426950408889634f;
    float t = fmaf(x, L2E, 12582912.0f);       // round-to-nearest-int via magic
    float n = t - 12582912.0f;                 // n = round(x*log2e)
    float f = fmaf(x, L2E, -n);                // f in [-0.5, 0.5]
    float p = 1.5403530393381608e-4f;          // 2^f Taylor (ln2^k/k!)
    p = fmaf(p, f, 1.3333558146428443e-3f);
    p = fmaf(p, f, 9.6181291076284772e-3f);
    p = fmaf(p, f, 5.5504108664821580e-2f);
    p = fmaf(p, f, 2.4022650695910072e-1f);
    p = fmaf(p, f, 6.9314718055994531e-1f);
    p = fmaf(p, f, 1.0f);
    int e = (int)n;                            // e in [-116, 0] after clamp
    float s = __int_as_float((127 + e) << 23);
    return p * s;
}

// ---------------------------------------------------------------------------
// Transposes: [B,C,H,W] <-> [B,HW,C]
// ---------------------------------------------------------------------------
__global__ void transpose_in_kernel(const float* __restrict__ x, float* __restrict__ img) {
    __shared__ float tile[32][33];
    int b = blockIdx.z;
    int hw0 = blockIdx.x * 32, c0 = blockIdx.y * 32;
    const float* src = x + (size_t)b * CH * HW;
    float* dst = img + (size_t)b * HW * CH;
    #pragma unroll
    for (int i = threadIdx.y; i < 32; i += 8)
        tile[i][threadIdx.x] = src[(size_t)(c0 + i) * HW + hw0 + threadIdx.x];
    __syncthreads();
    #pragma unroll
    for (int i = threadIdx.y; i < 32; i += 8)
        dst[(size_t)(hw0 + i) * CH + c0 + threadIdx.x] = tile[threadIdx.x][i];
}

__global__ void transpose_out_kernel(const float* __restrict__ img, float* __restrict__ x) {
    __shared__ float tile[32][33];
    int b = blockIdx.z;
    int hw0 = blockIdx.x * 32, c0 = blockIdx.y * 32;
    const float* src = img + (size_t)b * HW * CH;
    float* dst = x + (size_t)b * CH * HW;
    #pragma unroll
    for (int i = threadIdx.y; i < 32; i += 8)
        tile[i][threadIdx.x] = src[(size_t)(hw0 + i) * CH + c0 + threadIdx.x];
    __syncthreads();
    #pragma unroll
    for (int i = threadIdx.y; i < 32; i += 8)
        dst[(size_t)(c0 + i) * HW + hw0 + threadIdx.x] = tile[threadIdx.x][i];
}

// ---------------------------------------------------------------------------
// Fused window attention: gather + qkv + softmax(+bias,+mask) + AV + proj +
// residual + LayerNorm + scatter. One CTA per window, 256 threads.
// Shifted layer: shift folded into gather/scatter addressing (roll cancels).
// smem floats: Xs 64*97 | QKV 64*289 | S 64*65 | Ob 64*97 | WB 9216 | stats 128
// ---------------------------------------------------------------------------
#define ATTN_SMEM ((64*97 + 64*289 + 64*65 + 64*97 + 9216 + 128) * 4)

template<int SHIFTED>
__global__ void __launch_bounds__(256, 1) attn_kernel(
    const float* __restrict__ in, float* __restrict__ out,
    const float* __restrict__ wqkv, const float* __restrict__ bqkv,
    const float* __restrict__ table, const float* __restrict__ wproj,
    const float* __restrict__ bproj, const float* __restrict__ gam,
    const float* __restrict__ beta)
{
    extern __shared__ float sm[];
    float* Xs    = sm;                 // stride 97
    float* QKV   = Xs + 64*97;         // stride 289 (odd: conflict-free col access)
    float* S     = QKV + 64*289;       // stride 65
    float* Ob    = S + 64*65;          // stride 97
    float* WB    = Ob + 64*97;         // 9216 floats (32x288 tile or 96x96)
    float* stats = WB + 9216;          // mean[64], rstd[64]

    const int tid = threadIdx.x;
    const int wid = blockIdx.x;
    const int b  = wid / NWIN_PER;
    const int wl = wid - b * NWIN_PER;
    const int wr = wl / 24, wc = wl - (wl / 24) * 24;
    const float* src = in  + (size_t)b * HW * CH;
    float*       dst = out + (size_t)b * HW * CH;

    // ---- gather window tokens ----
    for (int idx = tid; idx < NTOK * CH; idx += 256) {
        int t = idx / CH, c = idx - t * CH;
        int r = t >> 3, cl = t & 7;
        int h = wr * 8 + r, w = wc * 8 + cl;
        if (SHIFTED) { h += 4; if (h >= HH) h -= HH; w += 4; if (w >= WWI) w -= WWI; }
        Xs[t * 97 + c] = src[(h * WWI + w) * CH + c];
    }
    __syncthreads();

    const int ty = tid >> 5, tx = tid & 31;

    // ---- QKV GEMM: 64x96 @ 96x288, 8 rows x 9 cols per thread ----
    float acc[8][9];
    #pragma unroll
    for (int j = 0; j < 9; j++) {
        float bj = bqkv[tx + 32 * j];
        #pragma unroll
        for (int r = 0; r < 8; r++) acc[r][j] = bj;
    }
    for (int kt = 0; kt < 3; kt++) {
        for (int idx = tid; idx < 32 * 288; idx += 256)
            WB[idx] = wqkv[kt * 32 * 288 + idx];
        __syncthreads();
        #pragma unroll 2
        for (int k = 0; k < 32; k++) {
            float xf[8], wf[9];
            #pragma unroll
            for (int r = 0; r < 8; r++) xf[r] = Xs[(ty * 8 + r) * 97 + kt * 32 + k];
            #pragma unroll
            for (int j = 0; j < 9; j++) wf[j] = WB[k * 288 + tx + 32 * j];
            #pragma unroll
            for (int r = 0; r < 8; r++)
                #pragma unroll
                for (int j = 0; j < 9; j++)
                    acc[r][j] = fmaf(xf[r], wf[j], acc[r][j]);
        }
        __syncthreads();
    }
    #pragma unroll
    for (int r = 0; r < 8; r++)
        #pragma unroll
        for (int j = 0; j < 9; j++)
            QKV[(ty * 8 + r) * 289 + tx + 32 * j] = acc[r][j];
    __syncthreads();

    // ---- per-head attention ----
    for (int hd = 0; hd < NHEAD; hd++) {
        // scores: warp ty owns rows 8ty..8ty+7; lane tx owns cols tx, tx+32
        float sc[8][2];
        #pragma unroll
        for (int r = 0; r < 8; r++) { sc[r][0] = 0.f; sc[r][1] = 0.f; }
        #pragma unroll
        for (int d = 0; d < HDIM; d++) {
            float k0 = QKV[tx * 289 + 96 + hd * 16 + d];
            float k1 = QKV[(tx + 32) * 289 + 96 + hd * 16 + d];
            #pragma unroll
            for (int r = 0; r < 8; r++) {
                float q = QKV[(ty * 8 + r) * 289 + hd * 16 + d];
                sc[r][0] = fmaf(q, k0, sc[r][0]);
                sc[r][1] = fmaf(q, k1, sc[r][1]);
            }
        }
        // bias + mask + shuffle softmax (row fully within one warp)
        #pragma unroll
        for (int r = 0; r < 8; r++) {
            int i = ty * 8 + r;
            int ri = i >> 3, ci = i & 7;
            float v[2];
            #pragma unroll
            for (int cj = 0; cj < 2; cj++) {
                int j = tx + 32 * cj;
                int rj = j >> 3, cjj = j & 7;
                int ridx = (ri - rj + 7) * 15 + (ci - cjj + 7);
                float bias = table[ridx * 6 + hd];
                if (SHIFTED) {
                    int cnti = ((wr == 23) ? (ri  < 4 ? 1 : 2) : 0) * 3
                             + ((wc == 23) ? (ci  < 4 ? 1 : 2) : 0);
                    int cntj = ((wr == 23) ? (rj  < 4 ? 1 : 2) : 0) * 3
                             + ((wc == 23) ? (cjj < 4 ? 1 : 2) : 0);
                    if (cnti != cntj) bias -= 100.f;
                }
                v[cj] = fmaf(sc[r][cj], 0.25f, bias);
            }
            float mx = fmaxf(v[0], v[1]);
            #pragma unroll
            for (int o = 16; o > 0; o >>= 1) mx = fmaxf(mx, __shfl_xor_sync(0xffffffffu, mx, o));
            float e0 = fexp(v[0] - mx), e1 = fexp(v[1] - mx);
            float ssum = e0 + e1;
            #pragma unroll
            for (int o = 16; o > 0; o >>= 1) ssum += __shfl_xor_sync(0xffffffffu, ssum, o);
            float inv = 1.0f / ssum;
            S[i * 65 + tx]      = e0 * inv;
            S[i * 65 + tx + 32] = e1 * inv;
        }
        __syncthreads();
        // attn @ V: thread owns (4 rows, 1 dim)
        {
            int d  = tid & 15;
            int ib = (tid >> 4) * 4;
            float o0 = 0.f, o1 = 0.f, o2 = 0.f, o3 = 0.f;
            #pragma unroll 4
            for (int j = 0; j < 64; j++) {
                float vv = QKV[j * 289 + 192 + hd * 16 + d];
                o0 = fmaf(S[(ib + 0) * 65 + j], vv, o0);
                o1 = fmaf(S[(ib + 1) * 65 + j], vv, o1);
                o2 = fmaf(S[(ib + 2) * 65 + j], vv, o2);
                o3 = fmaf(S[(ib + 3) * 65 + j], vv, o3);
            }
            Ob[(ib + 0) * 97 + hd * 16 + d] = o0;
            Ob[(ib + 1) * 97 + hd * 16 + d] = o1;
            Ob[(ib + 2) * 97 + hd * 16 + d] = o2;
            Ob[(ib + 3) * 97 + hd * 16 + d] = o3;
        }
        __syncthreads();
    }

    // ---- proj GEMM 64x96 @ 96x96 + residual ----
    for (int idx = tid; idx < 96 * 96; idx += 256) WB[idx] = wproj[idx];
    __syncthreads();
    float pa[8][3];
    #pragma unroll
    for (int j = 0; j < 3; j++) {
        float bj = bproj[tx + 32 * j];
        #pragma unroll
        for (int r = 0; r < 8; r++) pa[r][j] = bj;
    }
    #pragma unroll 2
    for (int k = 0; k < 96; k++) {
        float of[8], wf[3];
        #pragma unroll
        for (int r = 0; r < 8; r++) of[r] = Ob[(ty * 8 + r) * 97 + k];
        #pragma unroll
        for (int j = 0; j < 3; j++) wf[j] = WB[k * 96 + tx + 32 * j];
        #pragma unroll
        for (int r = 0; r < 8; r++)
            #pragma unroll
            for (int j = 0; j < 3; j++)
                pa[r][j] = fmaf(of[r], wf[j], pa[r][j]);
    }
    float* Y = QKV;  // reuse (stride 97); all QKV reads finished
    #pragma unroll
    for (int r = 0; r < 8; r++)
        #pragma unroll
        for (int j = 0; j < 3; j++) {
            int i = ty * 8 + r, c = tx + 32 * j;
            Y[i * 97 + c] = pa[r][j] + Xs[i * 97 + c];
        }
    __syncthreads();

    // ---- LayerNorm ----
    if (tid < 64) {
        float s = 0.f;
        #pragma unroll 4
        for (int c = 0; c < 96; c++) s += Y[tid * 97 + c];
        float mean = s * (1.0f / 96.0f);
        float v = 0.f;
        #pragma unroll 4
        for (int c = 0; c < 96; c++) { float dd = Y[tid * 97 + c] - mean; v = fmaf(dd, dd, v); }
        stats[tid]      = mean;
        stats[64 + tid] = rsqrtf(v * (1.0f / 96.0f) + 1e-5f);
    }
    __syncthreads();

    // ---- scatter (same coords as gather: roll cancels) ----
    for (int idx = tid; idx < NTOK * CH; idx += 256) {
        int t = idx / CH, c = idx - t * CH;
        int r = t >> 3, cl = t & 7;
        int h = wr * 8 + r, w = wc * 8 + cl;
        if (SHIFTED) { h += 4; if (h >= HH) h -= HH; w += 4; if (w >= WWI) w -= WWI; }
        float yv = (Y[t * 97 + c] - stats[t]) * stats[64 + t];
        dst[(h * WWI + w) * CH + c] = fmaf(yv, gam[c], beta[c]);
    }
}

// ---------------------------------------------------------------------------
// Fused FFN: x@W1+b1 -> gelu(erf) -> @W2+b2 -> +residual -> LayerNorm
// 64 tokens per CTA, 256 threads. Per-token op, fully coalesced I/O.
// smem floats: Xs 6144 | H1 12288 | WB 18432 | Y 64*97 | stats 128
// ---------------------------------------------------------------------------
#define FFN_SMEM ((6144 + 12288 + 18432 + 64*97 + 128) * 4)

__global__ void __launch_bounds__(256, 1) ffn_kernel(
    const float* __restrict__ in, float* __restrict__ out,
    const float* __restrict__ w1, const float* __restrict__ b1,
    const float* __restrict__ w2, const float* __restrict__ b2,
    const float* __restrict__ gam, const float* __restrict__ beta)
{
    extern __shared__ float sm[];
    float* Xs    = sm;                  // 64 x 96
    float* H1    = Xs + 6144;           // 64 x 192
    float* WB    = H1 + 12288;          // 96x192 then 192x96
    float* Y     = WB + 18432;          // 64 x 97
    float* stats = Y + 64 * 97;

    const int tid = threadIdx.x;
    const size_t t0 = (size_t)blockIdx.x * 64;
    const float* src = in + t0 * CH;
    float*       dst = out + t0 * CH;

    for (int idx = tid; idx < 6144; idx += 256) Xs[idx] = src[idx];
    for (int idx = tid; idx < 18432; idx += 256) WB[idx] = w1[idx];
    __syncthreads();

    const int ty = tid >> 5, tx = tid & 31;

    // GEMM1: 64x96 @ 96x192, 8x6 per thread
    float a1[8][6];
    #pragma unroll
    for (int j = 0; j < 6; j++) {
        float bj = b1[tx + 32 * j];
        #pragma unroll
        for (int r = 0; r < 8; r++) a1[r][j] = bj;
    }
    #pragma unroll 2
    for (int k = 0; k < 96; k++) {
        float xf[8], wf[6];
        #pragma unroll
        for (int r = 0; r < 8; r++) xf[r] = Xs[(ty * 8 + r) * 96 + k];
        #pragma unroll
        for (int j = 0; j < 6; j++) wf[j] = WB[k * 192 + tx + 32 * j];
        #pragma unroll
        for (int r = 0; r < 8; r++)
            #pragma unroll
            for (int j = 0; j < 6; j++)
                a1[r][j] = fmaf(xf[r], wf[j], a1[r][j]);
    }
    #pragma unroll
    for (int r = 0; r < 8; r++)
        #pragma unroll
        for (int j = 0; j < 6; j++) {
            float x = a1[r][j];
            float g = 0.5f * x * (1.0f + erff(x * 0.70710678118654752f));
            H1[(ty * 8 + r) * 192 + tx + 32 * j] = g;
        }
    __syncthreads();
    for (int idx = tid; idx < 18432; idx += 256) WB[idx] = w2[idx];
    __syncthreads();

    // GEMM2: 64x192 @ 192x96, 8x3 per thread
    float a2[8][3];
    #pragma unroll
    for (int j = 0; j < 3; j++) {
        float bj = b2[tx + 32 * j];
        #pragma unroll
        for (int r = 0; r < 8; r++) a2[r][j] = bj;
    }
    #pragma unroll 2
    for (int k = 0; k < 192; k++) {
        float hf[8], wf[3];
        #pragma unroll
        for (int r = 0; r < 8; r++) hf[r] = H1[(ty * 8 + r) * 192 + k];
        #pragma unroll
        for (int j = 0; j < 3; j++) wf[j] = WB[k * 96 + tx + 32 * j];
        #pragma unroll
        for (int r = 0; r < 8; r++)
            #pragma unroll
            for (int j = 0; j < 3; j++)
                a2[r][j] = fmaf(hf[r], wf[j], a2[r][j]);
    }
    #pragma unroll
    for (int r = 0; r < 8; r++)
        #pragma unroll
        for (int j = 0; j < 3; j++) {
            int i = ty * 8 + r, c = tx + 32 * j;
            Y[i * 97 + c] = a2[r][j] + Xs[i * 96 + c];
        }
    __syncthreads();

    if (tid < 64) {
        float s = 0.f;
        #pragma unroll 4
        for (int c = 0; c < 96; c++) s += Y[tid * 97 + c];
        float mean = s * (1.0f / 96.0f);
        float v = 0.f;
        #pragma unroll 4
        for (int c = 0; c < 96; c++) { float dd = Y[tid * 97 + c] - mean; v = fmaf(dd, dd, v); }
        stats[tid]      = mean;
        stats[64 + tid] = rsqrtf(v * (1.0f / 96.0f) + 1e-5f);
    }
    __syncthreads();

    for (int idx = tid; idx < 6144; idx += 256) {
        int t = idx / CH, c = idx - t * CH;
        float yv = (Y[t * 97 + c] - stats[t]) * stats[64 + t];
        dst[idx] = fmaf(yv, gam[c], beta[c]);
    }
}

// ---------------------------------------------------------------------------
// Input order follows setup_inputs() dict insertion order:
//   0: x | 1..7: sa1 (wqkv,bqkv,table,wproj,bproj,g,b)
//   8..14: sa2 | 15..20: ff1 (w1,b1,w2,b2,g,b) | 21..26: ff2
// ---------------------------------------------------------------------------
extern "C" void kernel_launch(void* const* d_in, const int* in_sizes, int n_in,
                              void* d_out, int out_size) {
    const float* x = (const float*)d_in[0];
    float *imgA, *imgB;
    cudaGetSymbolAddress((void**)&imgA, g_imgA);
    cudaGetSymbolAddress((void**)&imgB, g_imgB);

    cudaFuncSetAttribute(attn_kernel<0>, cudaFuncAttributeMaxDynamicSharedMemorySize, ATTN_SMEM);
    cudaFuncSetAttribute(attn_kernel<1>, cudaFuncAttributeMaxDynamicSharedMemorySize, ATTN_SMEM);
    cudaFuncSetAttribute(ffn_kernel,     cudaFuncAttributeMaxDynamicSharedMemorySize, FFN_SMEM);

    dim3 tb(32, 8);
    dim3 tg(HW / 32, CH / 32, BATCH);

    transpose_in_kernel<<<tg, tb>>>(x, imgA);

    attn_kernel<0><<<NWIN, 256, ATTN_SMEM>>>(
        imgA, imgB,
        (const float*)d_in[1], (const float*)d_in[2], (const float*)d_in[3],
        (const float*)d_in[4], (const float*)d_in[5], (const float*)d_in[6],
        (const float*)d_in[7]);

    ffn_kernel<<<NWIN, 256, FFN_SMEM>>>(
        imgB, imgA,
        (const float*)d_in[15], (const float*)d_in[16], (const float*)d_in[17],
        (const float*)d_in[18], (const float*)d_in[19], (const float*)d_in[20]);

    attn_kernel<1><<<NWIN, 256, ATTN_SMEM>>>(
        imgA, imgB,
        (const float*)d_in[8], (const float*)d_in[9], (const float*)d_in[10],
        (const float*)d_in[11], (const float*)d_in[12], (const float*)d_in[13],
        (const float*)d_in[14]);

    ffn_kernel<<<NWIN, 256, FFN_SMEM>>>(
        imgB, imgA,
        (const float*)d_in[21], (const float*)d_in[22], (const float*)d_in[23],
        (const float*)d_in[24], (const float*)d_in[25], (const float*)d_in[26]);

    transpose_out_kernel<<<tg, tb>>>(imgA, (float*)d_out);
}

// round 5
// speedup vs baseline: 1.1259x; 1.1259x over previous
#include <cuda_runtime.h>
#include <math.h>

#define CH    96
#define HH    192
#define WWI   192
#define HW    (HH*WWI)        // 36864
#define BATCH 4
#define NWIN_PER 576          // 24*24 windows per image
#define NWIN  (BATCH*NWIN_PER)
#define NTOK  64
#define NHEAD 6
#define HDIM  16
#define QS    100             // Q/K/V/Ob/Y row stride (odd 16B-granule stride)

// 56.6 MB each — static device scratch (no allocations allowed)
__device__ float g_imgA[BATCH*HW*CH];
__device__ float g_imgB[BATCH*HW*CH];

// ---------------------------------------------------------------------------
// FMA-only exp. Valid for x <= 0 (softmax-shifted logits); clamps at -80.
// ---------------------------------------------------------------------------
__device__ __forceinline__ float fexp(float x) {
    x = fmaxf(x, -80.0f);
    const float L2E = 1.4426950408889634f;
    float t = fmaf(x, L2E, 12582912.0f);
    float n = t - 12582912.0f;
    float f = fmaf(x, L2E, -n);
    float p = 1.5403530393381608e-4f;
    p = fmaf(p, f, 1.3333558146428443e-3f);
    p = fmaf(p, f, 9.6181291076284772e-3f);
    p = fmaf(p, f, 5.5504108664821580e-2f);
    p = fmaf(p, f, 2.4022650695910072e-1f);
    p = fmaf(p, f, 6.9314718055994531e-1f);
    p = fmaf(p, f, 1.0f);
    int e = (int)n;
    float s = __int_as_float((127 + e) << 23);
    return p * s;
}

// ---------------------------------------------------------------------------
// Transposes: [B,C,H,W] <-> [B,HW,C]
// ---------------------------------------------------------------------------
__global__ void transpose_in_kernel(const float* __restrict__ x, float* __restrict__ img) {
    __shared__ float tile[32][33];
    int b = blockIdx.z;
    int hw0 = blockIdx.x * 32, c0 = blockIdx.y * 32;
    const float* src = x + (size_t)b * CH * HW;
    float* dst = img + (size_t)b * HW * CH;
    #pragma unroll
    for (int i = threadIdx.y; i < 32; i += 8)
        tile[i][threadIdx.x] = src[(size_t)(c0 + i) * HW + hw0 + threadIdx.x];
    __syncthreads();
    #pragma unroll
    for (int i = threadIdx.y; i < 32; i += 8)
        dst[(size_t)(hw0 + i) * CH + c0 + threadIdx.x] = tile[threadIdx.x][i];
}

__global__ void transpose_out_kernel(const float* __restrict__ img, float* __restrict__ x) {
    __shared__ float tile[32][33];
    int b = blockIdx.z;
    int hw0 = blockIdx.x * 32, c0 = blockIdx.y * 32;
    const float* src = img + (size_t)b * HW * CH;
    float* dst = x + (size_t)b * CH * HW;
    #pragma unroll
    for (int i = threadIdx.y; i < 32; i += 8)
        tile[i][threadIdx.x] = src[(size_t)(hw0 + i) * CH + c0 + threadIdx.x];
    __syncthreads();
    #pragma unroll
    for (int i = threadIdx.y; i < 32; i += 8)
        dst[(size_t)(c0 + i) * HW + hw0 + threadIdx.x] = tile[threadIdx.x][i];
}

// ---------------------------------------------------------------------------
// Fused window attention, 512 threads / CTA (16 warps), float4 smem traffic.
// smem floats: Xs 6400 | Qb 6400 | Kb 6400 | Vb 6400 | S 2*64*68 | Ob 6400
//              | WB 9216 | stats 128  => 50,048 floats = 200,192 B
// ---------------------------------------------------------------------------
#define ATTN_SMEM (50048 * 4)

template<int SHIFTED>
__global__ void __launch_bounds__(512, 1) attn_kernel(
    const float* __restrict__ in, float* __restrict__ out,
    const float* __restrict__ wqkv, const float* __restrict__ bqkv,
    const float* __restrict__ table, const float* __restrict__ wproj,
    const float* __restrict__ bproj, const float* __restrict__ gam,
    const float* __restrict__ beta)
{
    extern __shared__ float sm[];
    float* Xs    = sm;                 // 64 x QS
    float* Qb    = Xs + 64*QS;         // 64 x QS (later reused as Y)
    float* Kb    = Qb + 64*QS;
    float* Vb    = Kb + 64*QS;
    float* S     = Vb + 64*QS;         // 2 x 64 x 68
    float* Ob    = S + 2*64*68;        // 64 x QS
    float* WB    = Ob + 64*QS;         // 9216
    float* stats = WB + 9216;

    const int tid = threadIdx.x;
    const int wid = blockIdx.x;
    const int b  = wid / NWIN_PER;
    const int wl = wid - b * NWIN_PER;
    const int wr = wl / 24, wc = wl - (wl / 24) * 24;
    const float* src = in  + (size_t)b * HW * CH;
    float*       dst = out + (size_t)b * HW * CH;

    // ---- gather window tokens ----
    for (int idx = tid; idx < NTOK * CH; idx += 512) {
        int t = idx / CH, c = idx - t * CH;
        int r = t >> 3, cl = t & 7;
        int h = wr * 8 + r, w = wc * 8 + cl;
        if (SHIFTED) { h += 4; if (h >= HH) h -= HH; w += 4; if (w >= WWI) w -= WWI; }
        Xs[t * QS + c] = src[(h * WWI + w) * CH + c];
    }
    __syncthreads();

    const int wg = tid >> 5, tx = tid & 31;   // 16 warps
    const int r0 = wg * 4;                    // 4 rows per warp

    // ---- QKV GEMM: 64x96 @ 96x288, 4 rows x 9 cols per thread ----
    float acc[4][9];
    #pragma unroll
    for (int j = 0; j < 9; j++) {
        float bj = bqkv[tx + 32 * j];
        #pragma unroll
        for (int r = 0; r < 4; r++) acc[r][j] = bj;
    }
    for (int kt = 0; kt < 3; kt++) {
        for (int idx = tid; idx < 32 * 288; idx += 512)
            WB[idx] = wqkv[kt * 32 * 288 + idx];
        __syncthreads();
        #pragma unroll
        for (int k4 = 0; k4 < 8; k4++) {
            float4 xf[4];
            #pragma unroll
            for (int r = 0; r < 4; r++)
                xf[r] = *(const float4*)&Xs[(r0 + r) * QS + kt * 32 + k4 * 4];
            #pragma unroll
            for (int kk = 0; kk < 4; kk++) {
                float wf[9];
                #pragma unroll
                for (int j = 0; j < 9; j++) wf[j] = WB[(k4 * 4 + kk) * 288 + tx + 32 * j];
                #pragma unroll
                for (int r = 0; r < 4; r++) {
                    float xv = (kk == 0) ? xf[r].x : (kk == 1) ? xf[r].y : (kk == 2) ? xf[r].z : xf[r].w;
                    #pragma unroll
                    for (int j = 0; j < 9; j++)
                        acc[r][j] = fmaf(xv, wf[j], acc[r][j]);
                }
            }
        }
        __syncthreads();
    }
    #pragma unroll
    for (int r = 0; r < 4; r++)
        #pragma unroll
        for (int j = 0; j < 9; j++) {
            int c = tx + 32 * j;
            int row = r0 + r;
            if (j < 3)      Qb[row * QS + c]       = acc[r][j];
            else if (j < 6) Kb[row * QS + (c - 96)] = acc[r][j];
            else            Vb[row * QS + (c - 192)] = acc[r][j];
        }
    __syncthreads();

    // ---- heads: 2 in flight (warps 0-7 -> head 2it, warps 8-15 -> 2it+1) ----
    for (int it = 0; it < 3; it++) {
        const int g   = wg >> 3;          // head group 0/1
        const int hd  = it * 2 + g;
        const int ty2 = wg & 7;
        const int i0  = ty2 * 8;
        float* Sg = S + g * 64 * 68;

        float sc[8][2];
        #pragma unroll
        for (int r = 0; r < 8; r++) { sc[r][0] = 0.f; sc[r][1] = 0.f; }
        #pragma unroll
        for (int d4 = 0; d4 < 4; d4++) {
            float4 k0 = *(const float4*)&Kb[tx * QS + hd * 16 + d4 * 4];
            float4 k1 = *(const float4*)&Kb[(tx + 32) * QS + hd * 16 + d4 * 4];
            #pragma unroll
            for (int r = 0; r < 8; r++) {
                float4 q = *(const float4*)&Qb[(i0 + r) * QS + hd * 16 + d4 * 4];
                sc[r][0] = fmaf(q.x, k0.x, fmaf(q.y, k0.y, fmaf(q.z, k0.z, fmaf(q.w, k0.w, sc[r][0]))));
                sc[r][1] = fmaf(q.x, k1.x, fmaf(q.y, k1.y, fmaf(q.z, k1.z, fmaf(q.w, k1.w, sc[r][1]))));
            }
        }
        #pragma unroll
        for (int r = 0; r < 8; r++) {
            int i = i0 + r;
            int ri = i >> 3, ci = i & 7;
            float v[2];
            #pragma unroll
            for (int cj = 0; cj < 2; cj++) {
                int j = tx + 32 * cj;
                int rj = j >> 3, cjj = j & 7;
                int ridx = (ri - rj + 7) * 15 + (ci - cjj + 7);
                float bias = table[ridx * 6 + hd];
                if (SHIFTED) {
                    int cnti = ((wr == 23) ? (ri  < 4 ? 1 : 2) : 0) * 3
                             + ((wc == 23) ? (ci  < 4 ? 1 : 2) : 0);
                    int cntj = ((wr == 23) ? (rj  < 4 ? 1 : 2) : 0) * 3
                             + ((wc == 23) ? (cjj < 4 ? 1 : 2) : 0);
                    if (cnti != cntj) bias -= 100.f;
                }
                v[cj] = fmaf(sc[r][cj], 0.25f, bias);
            }
            float mx = fmaxf(v[0], v[1]);
            #pragma unroll
            for (int o = 16; o > 0; o >>= 1) mx = fmaxf(mx, __shfl_xor_sync(0xffffffffu, mx, o));
            float e0 = fexp(v[0] - mx), e1 = fexp(v[1] - mx);
            float ssum = e0 + e1;
            #pragma unroll
            for (int o = 16; o > 0; o >>= 1) ssum += __shfl_xor_sync(0xffffffffu, ssum, o);
            float inv = 1.0f / ssum;
            Sg[i * 68 + tx]      = e0 * inv;
            Sg[i * 68 + tx + 32] = e1 * inv;
        }
        __syncthreads();

        // ---- attn @ V : thread = (row, d4 group) within its head's 256 threads ----
        {
            int gtid = tid & 255;
            int d4   = gtid & 3;
            int row  = gtid >> 2;
            float4 o = make_float4(0.f, 0.f, 0.f, 0.f);
            #pragma unroll 4
            for (int j4 = 0; j4 < 16; j4++) {
                float4 s4 = *(const float4*)&Sg[row * 68 + j4 * 4];
                #pragma unroll
                for (int jj = 0; jj < 4; jj++) {
                    float sj = (jj == 0) ? s4.x : (jj == 1) ? s4.y : (jj == 2) ? s4.z : s4.w;
                    float4 v4 = *(const float4*)&Vb[(j4 * 4 + jj) * QS + hd * 16 + d4 * 4];
                    o.x = fmaf(sj, v4.x, o.x);
                    o.y = fmaf(sj, v4.y, o.y);
                    o.z = fmaf(sj, v4.z, o.z);
                    o.w = fmaf(sj, v4.w, o.w);
                }
            }
            *(float4*)&Ob[row * QS + hd * 16 + d4 * 4] = o;
        }
        __syncthreads();
    }

    // ---- proj GEMM 64x96 @ 96x96 + residual ----
    for (int idx = tid; idx < 96 * 96; idx += 512) WB[idx] = wproj[idx];
    __syncthreads();
    float pa[4][3];
    #pragma unroll
    for (int j = 0; j < 3; j++) {
        float bj = bproj[tx + 32 * j];
        #pragma unroll
        for (int r = 0; r < 4; r++) pa[r][j] = bj;
    }
    #pragma unroll 2
    for (int k4 = 0; k4 < 24; k4++) {
        float4 of[4];
        #pragma unroll
        for (int r = 0; r < 4; r++)
            of[r] = *(const float4*)&Ob[(r0 + r) * QS + k4 * 4];
        #pragma unroll
        for (int kk = 0; kk < 4; kk++) {
            float wf[3];
            #pragma unroll
            for (int j = 0; j < 3; j++) wf[j] = WB[(k4 * 4 + kk) * 96 + tx + 32 * j];
            #pragma unroll
            for (int r = 0; r < 4; r++) {
                float ov = (kk == 0) ? of[r].x : (kk == 1) ? of[r].y : (kk == 2) ? of[r].z : of[r].w;
                #pragma unroll
                for (int j = 0; j < 3; j++)
                    pa[r][j] = fmaf(ov, wf[j], pa[r][j]);
            }
        }
    }
    float* Y = Qb;  // reuse
    __syncthreads(); // ensure all Q reads done before overwrite
    #pragma unroll
    for (int r = 0; r < 4; r++)
        #pragma unroll
        for (int j = 0; j < 3; j++) {
            int i = r0 + r, c = tx + 32 * j;
            Y[i * QS + c] = pa[r][j] + Xs[i * QS + c];
        }
    __syncthreads();

    // ---- LayerNorm ----
    if (tid < 64) {
        float s = 0.f;
        #pragma unroll
        for (int c4 = 0; c4 < 24; c4++) {
            float4 y = *(const float4*)&Y[tid * QS + c4 * 4];
            s += (y.x + y.y) + (y.z + y.w);
        }
        float mean = s * (1.0f / 96.0f);
        float v = 0.f;
        #pragma unroll
        for (int c4 = 0; c4 < 24; c4++) {
            float4 y = *(const float4*)&Y[tid * QS + c4 * 4];
            float d0 = y.x - mean, d1 = y.y - mean, d2 = y.z - mean, d3 = y.w - mean;
            v = fmaf(d0, d0, fmaf(d1, d1, fmaf(d2, d2, fmaf(d3, d3, v))));
        }
        stats[tid]      = mean;
        stats[64 + tid] = rsqrtf(v * (1.0f / 96.0f) + 1e-5f);
    }
    __syncthreads();

    // ---- scatter (same coords as gather: roll cancels) ----
    for (int idx = tid; idx < NTOK * CH; idx += 512) {
        int t = idx / CH, c = idx - t * CH;
        int r = t >> 3, cl = t & 7;
        int h = wr * 8 + r, w = wc * 8 + cl;
        if (SHIFTED) { h += 4; if (h >= HH) h -= HH; w += 4; if (w >= WWI) w -= WWI; }
        float yv = (Y[t * QS + c] - stats[t]) * stats[64 + t];
        dst[(h * WWI + w) * CH + c] = fmaf(yv, gam[c], beta[c]);
    }
}

// ---------------------------------------------------------------------------
// Fused FFN, 512 threads / CTA.
// smem floats: Xs 6144 | H1 12288 | WB 18432 | Y 6400 | stats 128 = 43,392
// ---------------------------------------------------------------------------
#define FFN_SMEM (43392 * 4)

__global__ void __launch_bounds__(512, 1) ffn_kernel(
    const float* __restrict__ in, float* __restrict__ out,
    const float* __restrict__ w1, const float* __restrict__ b1,
    const float* __restrict__ w2, const float* __restrict__ b2,
    const float* __restrict__ gam, const float* __restrict__ beta)
{
    extern __shared__ float sm[];
    float* Xs    = sm;                  // 64 x 96
    float* H1    = Xs + 6144;           // 64 x 192
    float* WB    = H1 + 12288;          // 96x192 then 192x96
    float* Y     = WB + 18432;          // 64 x QS
    float* stats = Y + 64 * QS;

    const int tid = threadIdx.x;
    const size_t t0 = (size_t)blockIdx.x * 64;
    const float* src = in + t0 * CH;
    float*       dst = out + t0 * CH;

    for (int idx = tid; idx < 6144; idx += 512) Xs[idx] = src[idx];
    for (int idx = tid; idx < 18432; idx += 512) WB[idx] = w1[idx];
    __syncthreads();

    const int wg = tid >> 5, tx = tid & 31;
    const int r0 = wg * 4;

    // GEMM1: 64x96 @ 96x192, 4x6 per thread
    float a1[4][6];
    #pragma unroll
    for (int j = 0; j < 6; j++) {
        float bj = b1[tx + 32 * j];
        #pragma unroll
        for (int r = 0; r < 4; r++) a1[r][j] = bj;
    }
    #pragma unroll 2
    for (int k4 = 0; k4 < 24; k4++) {
        float4 xf[4];
        #pragma unroll
        for (int r = 0; r < 4; r++)
            xf[r] = *(const float4*)&Xs[(r0 + r) * 96 + k4 * 4];
        #pragma unroll
        for (int kk = 0; kk < 4; kk++) {
            float wf[6];
            #pragma unroll
            for (int j = 0; j < 6; j++) wf[j] = WB[(k4 * 4 + kk) * 192 + tx + 32 * j];
            #pragma unroll
            for (int r = 0; r < 4; r++) {
                float xv = (kk == 0) ? xf[r].x : (kk == 1) ? xf[r].y : (kk == 2) ? xf[r].z : xf[r].w;
                #pragma unroll
                for (int j = 0; j < 6; j++)
                    a1[r][j] = fmaf(xv, wf[j], a1[r][j]);
            }
        }
    }
    #pragma unroll
    for (int r = 0; r < 4; r++)
        #pragma unroll
        for (int j = 0; j < 6; j++) {
            float x = a1[r][j];
            float g = 0.5f * x * (1.0f + erff(x * 0.70710678118654752f));
            H1[(r0 + r) * 192 + tx + 32 * j] = g;
        }
    __syncthreads();
    for (int idx = tid; idx < 18432; idx += 512) WB[idx] = w2[idx];
    __syncthreads();

    // GEMM2: 64x192 @ 192x96, 4x3 per thread
    float a2[4][3];
    #pragma unroll
    for (int j = 0; j < 3; j++) {
        float bj = b2[tx + 32 * j];
        #pragma unroll
        for (int r = 0; r < 4; r++) a2[r][j] = bj;
    }
    #pragma unroll 2
    for (int k4 = 0; k4 < 48; k4++) {
        float4 hf[4];
        #pragma unroll
        for (int r = 0; r < 4; r++)
            hf[r] = *(const float4*)&H1[(r0 + r) * 192 + k4 * 4];
        #pragma unroll
        for (int kk = 0; kk < 4; kk++) {
            float wf[3];
            #pragma unroll
            for (int j = 0; j < 3; j++) wf[j] = WB[(k4 * 4 + kk) * 96 + tx + 32 * j];
            #pragma unroll
            for (int r = 0; r < 4; r++) {
                float hv = (kk == 0) ? hf[r].x : (kk == 1) ? hf[r].y : (kk == 2) ? hf[r].z : hf[r].w;
                #pragma unroll
                for (int j = 0; j < 3; j++)
                    a2[r][j] = fmaf(hv, wf[j], a2[r][j]);
            }
        }
    }
    #pragma unroll
    for (int r = 0; r < 4; r++)
        #pragma unroll
        for (int j = 0; j < 3; j++) {
            int i = r0 + r, c = tx + 32 * j;
            Y[i * QS + c] = a2[r][j] + Xs[i * 96 + c];
        }
    __syncthreads();

    if (tid < 64) {
        float s = 0.f;
        #pragma unroll
        for (int c4 = 0; c4 < 24; c4++) {
            float4 y = *(const float4*)&Y[tid * QS + c4 * 4];
            s += (y.x + y.y) + (y.z + y.w);
        }
        float mean = s * (1.0f / 96.0f);
        float v = 0.f;
        #pragma unroll
        for (int c4 = 0; c4 < 24; c4++) {
            float4 y = *(const float4*)&Y[tid * QS + c4 * 4];
            float d0 = y.x - mean, d1 = y.y - mean, d2 = y.z - mean, d3 = y.w - mean;
            v = fmaf(d0, d0, fmaf(d1, d1, fmaf(d2, d2, fmaf(d3, d3, v))));
        }
        stats[tid]      = mean;
        stats[64 + tid] = rsqrtf(v * (1.0f / 96.0f) + 1e-5f);
    }
    __syncthreads();

    for (int idx = tid; idx < 6144; idx += 512) {
        int t = idx / CH, c = idx - t * CH;
        float yv = (Y[t * QS + c] - stats[t]) * stats[64 + t];
        dst[idx] = fmaf(yv, gam[c], beta[c]);
    }
}

// ---------------------------------------------------------------------------
// Input order (setup_inputs dict order):
//   0: x | 1..7: sa1 | 8..14: sa2 | 15..20: ff1 | 21..26: ff2
// ---------------------------------------------------------------------------
extern "C" void kernel_launch(void* const* d_in, const int* in_sizes, int n_in,
                              void* d_out, int out_size) {
    const float* x = (const float*)d_in[0];
    float *imgA, *imgB;
    cudaGetSymbolAddress((void**)&imgA, g_imgA);
    cudaGetSymbolAddress((void**)&imgB, g_imgB);

    cudaFuncSetAttribute(attn_kernel<0>, cudaFuncAttributeMaxDynamicSharedMemorySize, ATTN_SMEM);
    cudaFuncSetAttribute(attn_kernel<1>, cudaFuncAttributeMaxDynamicSharedMemorySize, ATTN_SMEM);
    cudaFuncSetAttribute(ffn_kernel,     cudaFuncAttributeMaxDynamicSharedMemorySize, FFN_SMEM);

    dim3 tb(32, 8);
    dim3 tg(HW / 32, CH / 32, BATCH);

    transpose_in_kernel<<<tg, tb>>>(x, imgA);

    attn_kernel<0><<<NWIN, 512, ATTN_SMEM>>>(
        imgA, imgB,
        (const float*)d_in[1], (const float*)d_in[2], (const float*)d_in[3],
        (const float*)d_in[4], (const float*)d_in[5], (const float*)d_in[6],
        (const float*)d_in[7]);

    ffn_kernel<<<NWIN, 512, FFN_SMEM>>>(
        imgB, imgA,
        (const float*)d_in[15], (const float*)d_in[16], (const float*)d_in[17],
        (const float*)d_in[18], (const float*)d_in[19], (const float*)d_in[20]);

    attn_kernel<1><<<NWIN, 512, ATTN_SMEM>>>(
        imgA, imgB,
        (const float*)d_in[8], (const float*)d_in[9], (const float*)d_in[10],
        (const float*)d_in[11], (const float*)d_in[12], (const float*)d_in[13],
        (const float*)d_in[14]);

    ffn_kernel<<<NWIN, 512, FFN_SMEM>>>(
        imgB, imgA,
        (const float*)d_in[21], (const float*)d_in[22], (const float*)d_in[23],
        (const float*)d_in[24], (const float*)d_in[25], (const float*)d_in[26]);

    transpose_out_kernel<<<tg, tb>>>(imgA, (float*)d_out);
}

// round 6
// speedup vs baseline: 1.2081x; 1.0730x over previous
#include <cuda_runtime.h>
#include <math.h>

#define CH    96
#define HH    192
#define WWI   192
#define HW    (HH*WWI)        // 36864
#define BATCH 4
#define NWIN_PER 576          // 24*24 windows per image
#define NWIN  (BATCH*NWIN_PER)
#define NTOK  64
#define NHEAD 6
#define HDIM  16
#define QS    100             // row stride for 64-row fp32 tiles

// 56.6 MB each — static device scratch (no allocations allowed)
__device__ float g_imgA[BATCH*HW*CH];
__device__ float g_imgB[BATCH*HW*CH];

// ---------------------------------------------------------------------------
// FMA-only exp. Valid for x <= 0 (softmax-shifted logits); clamps at -80.
// ---------------------------------------------------------------------------
__device__ __forceinline__ float fexp(float x) {
    x = fmaxf(x, -80.0f);
    const float L2E = 1.4426950408889634f;
    float t = fmaf(x, L2E, 12582912.0f);
    float n = t - 12582912.0f;
    float f = fmaf(x, L2E, -n);
    float p = 1.5403530393381608e-4f;
    p = fmaf(p, f, 1.3333558146428443e-3f);
    p = fmaf(p, f, 9.6181291076284772e-3f);
    p = fmaf(p, f, 5.5504108664821580e-2f);
    p = fmaf(p, f, 2.4022650695910072e-1f);
    p = fmaf(p, f, 6.9314718055994531e-1f);
    p = fmaf(p, f, 1.0f);
    int e = (int)n;
    float s = __int_as_float((127 + e) << 23);
    return p * s;
}

// ---------------------------------------------------------------------------
// Transposes: [B,C,H,W] <-> [B,HW,C]
// ---------------------------------------------------------------------------
__global__ void transpose_in_kernel(const float* __restrict__ x, float* __restrict__ img) {
    __shared__ float tile[32][33];
    int b = blockIdx.z;
    int hw0 = blockIdx.x * 32, c0 = blockIdx.y * 32;
    const float* src = x + (size_t)b * CH * HW;
    float* dst = img + (size_t)b * HW * CH;
    #pragma unroll
    for (int i = threadIdx.y; i < 32; i += 8)
        tile[i][threadIdx.x] = src[(size_t)(c0 + i) * HW + hw0 + threadIdx.x];
    __syncthreads();
    #pragma unroll
    for (int i = threadIdx.y; i < 32; i += 8)
        dst[(size_t)(hw0 + i) * CH + c0 + threadIdx.x] = tile[threadIdx.x][i];
}

__global__ void transpose_out_kernel(const float* __restrict__ img, float* __restrict__ x) {
    __shared__ float tile[32][33];
    int b = blockIdx.z;
    int hw0 = blockIdx.x * 32, c0 = blockIdx.y * 32;
    const float* src = img + (size_t)b * HW * CH;
    float* dst = x + (size_t)b * CH * HW;
    #pragma unroll
    for (int i = threadIdx.y; i < 32; i += 8)
        tile[i][threadIdx.x] = src[(size_t)(hw0 + i) * CH + c0 + threadIdx.x];
    __syncthreads();
    #pragma unroll
    for (int i = threadIdx.y; i < 32; i += 8)
        dst[(size_t)(c0 + i) * HW + hw0 + threadIdx.x] = tile[threadIdx.x][i];
}

// ---------------------------------------------------------------------------
// Fused window attention, 512 threads (16 warps), split-K GEMMs, LDG weights.
// smem floats: Xs/Qb/Kb/Vb/Ob 5*6400 | S 2*64*68 (also proj scratch) |
//              Tb 1360 | stats 128 | Cnt 64  = 42,256 floats = 169,024 B
// ---------------------------------------------------------------------------
#define ATTN_SMEM (42256 * 4)

template<int SHIFTED>
__global__ void __launch_bounds__(512, 1) attn_kernel(
    const float* __restrict__ in, float* __restrict__ out,
    const float* __restrict__ wqkv, const float* __restrict__ bqkv,
    const float* __restrict__ table, const float* __restrict__ wproj,
    const float* __restrict__ bproj, const float* __restrict__ gam,
    const float* __restrict__ beta)
{
    extern __shared__ float sm[];
    float* Xs    = sm;                 // 64 x QS
    float* Qb    = Xs + 64*QS;         // 64 x QS (later reused as Y)
    float* Kb    = Qb + 64*QS;
    float* Vb    = Kb + 64*QS;
    float* Ob    = Vb + 64*QS;
    float* S     = Ob + 64*QS;         // 2 x 64 x 68 ; also proj partial (64xQS? no: 64x96 fits)
    float* Tb    = S + 2*64*68;        // 1360 (1350 used)
    float* stats = Tb + 1360;          // 128
    int*   Cnt   = (int*)(stats + 128);// 64

    const int tid = threadIdx.x;
    const int wid = blockIdx.x;
    const int b  = wid / NWIN_PER;
    const int wl = wid - b * NWIN_PER;
    const int wr = wl / 24, wc = wl - (wl / 24) * 24;
    const float* src = in  + (size_t)b * HW * CH;
    float*       dst = out + (size_t)b * HW * CH;

    // ---- gather window tokens + stage table + region ids ----
    for (int idx = tid; idx < NTOK * CH; idx += 512) {
        int t = idx / CH, c = idx - t * CH;
        int r = t >> 3, cl = t & 7;
        int h = wr * 8 + r, w = wc * 8 + cl;
        if (SHIFTED) { h += 4; if (h >= HH) h -= HH; w += 4; if (w >= WWI) w -= WWI; }
        Xs[t * QS + c] = src[(h * WWI + w) * CH + c];
    }
    for (int idx = tid; idx < 1350; idx += 512) Tb[idx] = table[idx];
    if (SHIFTED && tid < 64) {
        int ri = tid >> 3, ci = tid & 7;
        Cnt[tid] = ((wr == 23) ? (ri < 4 ? 1 : 2) : 0) * 3
                 + ((wc == 23) ? (ci < 4 ? 1 : 2) : 0);
    }
    __syncthreads();

    const int wg = tid >> 5, tx = tid & 31;   // 16 warps
    const int rowg = wg & 7, kh = wg >> 3;
    const int r0 = rowg * 8;                  // 8 rows per warp
    const int kb = kh * 48;                   // split-K half

    // ---- QKV GEMM: 64x96 @ 96x288, split-K x2, B direct from gmem (L2) ----
    float acc[8][9];
    if (kh == 0) {
        #pragma unroll
        for (int j = 0; j < 9; j++) {
            float bj = bqkv[tx + 32 * j];
            #pragma unroll
            for (int r = 0; r < 8; r++) acc[r][j] = bj;
        }
    } else {
        #pragma unroll
        for (int r = 0; r < 8; r++)
            #pragma unroll
            for (int j = 0; j < 9; j++) acc[r][j] = 0.f;
    }
    #pragma unroll 2
    for (int k2 = 0; k2 < 24; k2++) {
        float2 xf[8];
        #pragma unroll
        for (int r = 0; r < 8; r++)
            xf[r] = *(const float2*)&Xs[(r0 + r) * QS + kb + k2 * 2];
        #pragma unroll
        for (int kk = 0; kk < 2; kk++) {
            const float* wrow = wqkv + (kb + k2 * 2 + kk) * 288 + tx;
            float wf[9];
            #pragma unroll
            for (int j = 0; j < 9; j++) wf[j] = __ldg(wrow + 32 * j);
            #pragma unroll
            for (int r = 0; r < 8; r++) {
                float xv = kk ? xf[r].y : xf[r].x;
                #pragma unroll
                for (int j = 0; j < 9; j++)
                    acc[r][j] = fmaf(xv, wf[j], acc[r][j]);
            }
        }
    }
    // split-K reduction through Q/K/V buffers
    if (kh == 1) {
        #pragma unroll
        for (int r = 0; r < 8; r++)
            #pragma unroll
            for (int j = 0; j < 9; j++) {
                int c = tx + 32 * j, row = r0 + r;
                if (j < 3)      Qb[row * QS + c]        = acc[r][j];
                else if (j < 6) Kb[row * QS + (c - 96)]  = acc[r][j];
                else            Vb[row * QS + (c - 192)] = acc[r][j];
            }
    }
    __syncthreads();
    if (kh == 0) {
        #pragma unroll
        for (int r = 0; r < 8; r++)
            #pragma unroll
            for (int j = 0; j < 9; j++) {
                int c = tx + 32 * j, row = r0 + r;
                float* p;
                if (j < 3)      p = &Qb[row * QS + c];
                else if (j < 6) p = &Kb[row * QS + (c - 96)];
                else            p = &Vb[row * QS + (c - 192)];
                *p += acc[r][j];
            }
    }
    __syncthreads();

    // ---- heads: 2 in flight (warps 0-7 -> head 2it, warps 8-15 -> 2it+1) ----
    const int g  = wg >> 3;          // head group
    const int i0 = rowg * 8;
    int cni[8], cj0 = 0, cj1 = 0;
    if (SHIFTED) {
        cj0 = Cnt[tx]; cj1 = Cnt[tx + 32];
        #pragma unroll
        for (int r = 0; r < 8; r++) cni[r] = Cnt[i0 + r];
    }
    for (int it = 0; it < 3; it++) {
        const int hd = it * 2 + g;
        float* Sg = S + g * 64 * 68;

        float sc[8][2];
        #pragma unroll
        for (int r = 0; r < 8; r++) { sc[r][0] = 0.f; sc[r][1] = 0.f; }
        #pragma unroll
        for (int d4 = 0; d4 < 4; d4++) {
            float4 k0 = *(const float4*)&Kb[tx * QS + hd * 16 + d4 * 4];
            float4 k1 = *(const float4*)&Kb[(tx + 32) * QS + hd * 16 + d4 * 4];
            #pragma unroll
            for (int r = 0; r < 8; r++) {
                float4 q = *(const float4*)&Qb[(i0 + r) * QS + hd * 16 + d4 * 4];
                sc[r][0] = fmaf(q.x, k0.x, fmaf(q.y, k0.y, fmaf(q.z, k0.z, fmaf(q.w, k0.w, sc[r][0]))));
                sc[r][1] = fmaf(q.x, k1.x, fmaf(q.y, k1.y, fmaf(q.z, k1.z, fmaf(q.w, k1.w, sc[r][1]))));
            }
        }
        #pragma unroll
        for (int r = 0; r < 8; r++) {
            int i = i0 + r;
            int ri = i >> 3, ci = i & 7;
            float v[2];
            #pragma unroll
            for (int cj = 0; cj < 2; cj++) {
                int j = tx + 32 * cj;
                int rj = j >> 3, cjj = j & 7;
                int ridx = (ri - rj + 7) * 15 + (ci - cjj + 7);
                float bias = Tb[ridx * 6 + hd];
                if (SHIFTED) {
                    int cjv = cj ? cj1 : cj0;
                    if (cni[r] != cjv) bias -= 100.f;
                }
                v[cj] = fmaf(sc[r][cj], 0.25f, bias);
            }
            float mx = fmaxf(v[0], v[1]);
            #pragma unroll
            for (int o = 16; o > 0; o >>= 1) mx = fmaxf(mx, __shfl_xor_sync(0xffffffffu, mx, o));
            float e0 = fexp(v[0] - mx), e1 = fexp(v[1] - mx);
            float ssum = e0 + e1;
            #pragma unroll
            for (int o = 16; o > 0; o >>= 1) ssum += __shfl_xor_sync(0xffffffffu, ssum, o);
            float inv = 1.0f / ssum;
            Sg[i * 68 + tx]      = e0 * inv;
            Sg[i * 68 + tx + 32] = e1 * inv;
        }
        __syncthreads();

        // ---- attn @ V : thread = (row, d4 group) within its head's 256 threads ----
        {
            int gtid = tid & 255;
            int d4   = gtid & 3;
            int row  = gtid >> 2;
            float4 o = make_float4(0.f, 0.f, 0.f, 0.f);
            #pragma unroll 4
            for (int j4 = 0; j4 < 16; j4++) {
                float4 s4 = *(const float4*)&Sg[row * 68 + j4 * 4];
                #pragma unroll
                for (int jj = 0; jj < 4; jj++) {
                    float sj = (jj == 0) ? s4.x : (jj == 1) ? s4.y : (jj == 2) ? s4.z : s4.w;
                    float4 v4 = *(const float4*)&Vb[(j4 * 4 + jj) * QS + hd * 16 + d4 * 4];
                    o.x = fmaf(sj, v4.x, o.x);
                    o.y = fmaf(sj, v4.y, o.y);
                    o.z = fmaf(sj, v4.z, o.z);
                    o.w = fmaf(sj, v4.w, o.w);
                }
            }
            *(float4*)&Ob[row * QS + hd * 16 + d4 * 4] = o;
        }
        __syncthreads();
    }

    // ---- proj GEMM 64x96 @ 96x96, split-K x2, B direct from gmem ----
    float pa[8][3];
    if (kh == 0) {
        #pragma unroll
        for (int j = 0; j < 3; j++) {
            float bj = bproj[tx + 32 * j];
            #pragma unroll
            for (int r = 0; r < 8; r++) pa[r][j] = bj;
        }
    } else {
        #pragma unroll
        for (int r = 0; r < 8; r++)
            #pragma unroll
            for (int j = 0; j < 3; j++) pa[r][j] = 0.f;
    }
    #pragma unroll 2
    for (int k4 = 0; k4 < 12; k4++) {
        float4 of[8];
        #pragma unroll
        for (int r = 0; r < 8; r++)
            of[r] = *(const float4*)&Ob[(r0 + r) * QS + kb + k4 * 4];
        #pragma unroll
        for (int kk = 0; kk < 4; kk++) {
            const float* wrow = wproj + (kb + k4 * 4 + kk) * 96 + tx;
            float wf[3];
            #pragma unroll
            for (int j = 0; j < 3; j++) wf[j] = __ldg(wrow + 32 * j);
            #pragma unroll
            for (int r = 0; r < 8; r++) {
                float ov = (kk == 0) ? of[r].x : (kk == 1) ? of[r].y : (kk == 2) ? of[r].z : of[r].w;
                #pragma unroll
                for (int j = 0; j < 3; j++)
                    pa[r][j] = fmaf(ov, wf[j], pa[r][j]);
            }
        }
    }
    float* Pc = S;   // proj partial scratch (64 x 96, stride QS fits in S space)
    if (kh == 1) {
        #pragma unroll
        for (int r = 0; r < 8; r++)
            #pragma unroll
            for (int j = 0; j < 3; j++)
                Pc[(r0 + r) * QS + tx + 32 * j] = pa[r][j];
    }
    __syncthreads();
    float* Y = Qb;   // reuse Q buffer as output accumulator
    if (kh == 0) {
        #pragma unroll
        for (int r = 0; r < 8; r++)
            #pragma unroll
            for (int j = 0; j < 3; j++) {
                int i = r0 + r, c = tx + 32 * j;
                Y[i * QS + c] = pa[r][j] + Pc[i * QS + c] + Xs[i * QS + c];
            }
    }
    __syncthreads();

    // ---- LayerNorm: 8 threads per row, single pass ----
    {
        int row = tid >> 3, l8 = tid & 7;
        float s = 0.f, s2 = 0.f;
        #pragma unroll
        for (int q = 0; q < 3; q++) {
            float4 y = *(const float4*)&Y[row * QS + l8 * 12 + q * 4];
            s += (y.x + y.y) + (y.z + y.w);
            s2 = fmaf(y.x, y.x, fmaf(y.y, y.y, fmaf(y.z, y.z, fmaf(y.w, y.w, s2))));
        }
        #pragma unroll
        for (int o = 4; o > 0; o >>= 1) {
            s  += __shfl_xor_sync(0xffffffffu, s,  o);
            s2 += __shfl_xor_sync(0xffffffffu, s2, o);
        }
        if (l8 == 0) {
            float mean = s * (1.0f / 96.0f);
            float var  = fmaf(-mean, mean, s2 * (1.0f / 96.0f));
            stats[row]      = mean;
            stats[64 + row] = rsqrtf(var + 1e-5f);
        }
    }
    __syncthreads();

    // ---- scatter (same coords as gather: roll cancels) ----
    for (int idx = tid; idx < NTOK * CH; idx += 512) {
        int t = idx / CH, c = idx - t * CH;
        int r = t >> 3, cl = t & 7;
        int h = wr * 8 + r, w = wc * 8 + cl;
        if (SHIFTED) { h += 4; if (h >= HH) h -= HH; w += 4; if (w >= WWI) w -= WWI; }
        float yv = (Y[t * QS + c] - stats[t]) * stats[64 + t];
        dst[(h * WWI + w) * CH + c] = fmaf(yv, gam[c], beta[c]);
    }
}

// ---------------------------------------------------------------------------
// Fused FFN, 512 threads, split-K GEMMs with staged weights.
// smem floats: Xs 64x100 | H1 64x196 | WB 18432 | Y 64x100 | stats 128 = 43,904
// ---------------------------------------------------------------------------
#define FFN_SMEM (43904 * 4)
#define HS 196

__global__ void __launch_bounds__(512, 1) ffn_kernel(
    const float* __restrict__ in, float* __restrict__ out,
    const float* __restrict__ w1, const float* __restrict__ b1,
    const float* __restrict__ w2, const float* __restrict__ b2,
    const float* __restrict__ gam, const float* __restrict__ beta)
{
    extern __shared__ float sm[];
    float* Xs    = sm;                  // 64 x QS
    float* H1    = Xs + 64*QS;          // 64 x HS
    float* WB    = H1 + 64*HS;          // 18432 (full W1, then full W2)
    float* Y     = WB + 18432;          // 64 x QS
    float* stats = Y + 64*QS;

    const int tid = threadIdx.x;
    const size_t t0 = (size_t)blockIdx.x * 64;
    const float* src = in + t0 * CH;
    float*       dst = out + t0 * CH;

    for (int idx = tid; idx < 6144; idx += 512) {
        int t = idx / CH, c = idx - t * CH;
        Xs[t * QS + c] = src[idx];
    }
    for (int idx = tid; idx < 18432; idx += 512) WB[idx] = w1[idx];
    __syncthreads();

    const int wg = tid >> 5, tx = tid & 31;
    const int rowg = wg & 7, kh = wg >> 3;
    const int r0 = rowg * 8;

    // GEMM1: 64x96 @ 96x192, split-K x2 (48 each), thread tile 8x6
    {
        const int kb = kh * 48;
        float a1[8][6];
        if (kh == 0) {
            #pragma unroll
            for (int j = 0; j < 6; j++) {
                float bj = b1[tx + 32 * j];
                #pragma unroll
                for (int r = 0; r < 8; r++) a1[r][j] = bj;
            }
        } else {
            #pragma unroll
            for (int r = 0; r < 8; r++)
                #pragma unroll
                for (int j = 0; j < 6; j++) a1[r][j] = 0.f;
        }
        #pragma unroll 2
        for (int k4 = 0; k4 < 12; k4++) {
            float4 xf[8];
            #pragma unroll
            for (int r = 0; r < 8; r++)
                xf[r] = *(const float4*)&Xs[(r0 + r) * QS + kb + k4 * 4];
            #pragma unroll
            for (int kk = 0; kk < 4; kk++) {
                float wf[6];
                #pragma unroll
                for (int j = 0; j < 6; j++) wf[j] = WB[(kb + k4 * 4 + kk) * 192 + tx + 32 * j];
                #pragma unroll
                for (int r = 0; r < 8; r++) {
                    float xv = (kk == 0) ? xf[r].x : (kk == 1) ? xf[r].y : (kk == 2) ? xf[r].z : xf[r].w;
                    #pragma unroll
                    for (int j = 0; j < 6; j++)
                        a1[r][j] = fmaf(xv, wf[j], a1[r][j]);
                }
            }
        }
        if (kh == 1) {
            #pragma unroll
            for (int r = 0; r < 8; r++)
                #pragma unroll
                for (int j = 0; j < 6; j++)
                    H1[(r0 + r) * HS + tx + 32 * j] = a1[r][j];
        }
        __syncthreads();
        if (kh == 0) {
            #pragma unroll
            for (int r = 0; r < 8; r++)
                #pragma unroll
                for (int j = 0; j < 6; j++) {
                    int c = tx + 32 * j;
                    float x = a1[r][j] + H1[(r0 + r) * HS + c];
                    float gl = 0.5f * x * (1.0f + erff(x * 0.70710678118654752f));
                    H1[(r0 + r) * HS + c] = gl;
                }
        }
        // stage W2 (WB reads for GEMM1 finished before previous sync)
        for (int idx = tid; idx < 18432; idx += 512) WB[idx] = w2[idx];
        __syncthreads();
    }

    // GEMM2: 64x192 @ 192x96, split-K x2 (96 each), thread tile 8x3
    {
        const int kb = kh * 96;
        float a2[8][3];
        if (kh == 0) {
            #pragma unroll
            for (int j = 0; j < 3; j++) {
                float bj = b2[tx + 32 * j];
                #pragma unroll
                for (int r = 0; r < 8; r++) a2[r][j] = bj;
            }
        } else {
            #pragma unroll
            for (int r = 0; r < 8; r++)
                #pragma unroll
                for (int j = 0; j < 3; j++) a2[r][j] = 0.f;
        }
        #pragma unroll 2
        for (int k4 = 0; k4 < 24; k4++) {
            float4 hf[8];
            #pragma unroll
            for (int r = 0; r < 8; r++)
                hf[r] = *(const float4*)&H1[(r0 + r) * HS + kb + k4 * 4];
            #pragma unroll
            for (int kk = 0; kk < 4; kk++) {
                float wf[3];
                #pragma unroll
                for (int j = 0; j < 3; j++) wf[j] = WB[(kb + k4 * 4 + kk) * 96 + tx + 32 * j];
                #pragma unroll
                for (int r = 0; r < 8; r++) {
                    float hv = (kk == 0) ? hf[r].x : (kk == 1) ? hf[r].y : (kk == 2) ? hf[r].z : hf[r].w;
                    #pragma unroll
                    for (int j = 0; j < 3; j++)
                        a2[r][j] = fmaf(hv, wf[j], a2[r][j]);
                }
            }
        }
        if (kh == 1) {
            #pragma unroll
            for (int r = 0; r < 8; r++)
                #pragma unroll
                for (int j = 0; j < 3; j++)
                    Y[(r0 + r) * QS + tx + 32 * j] = a2[r][j];
        }
        __syncthreads();
        if (kh == 0) {
            #pragma unroll
            for (int r = 0; r < 8; r++)
                #pragma unroll
                for (int j = 0; j < 3; j++) {
                    int i = r0 + r, c = tx + 32 * j;
                    Y[i * QS + c] = a2[r][j] + Y[i * QS + c] + Xs[i * QS + c];
                }
        }
        __syncthreads();
    }

    // LayerNorm: 8 threads per row, single pass
    {
        int row = tid >> 3, l8 = tid & 7;
        float s = 0.f, s2 = 0.f;
        #pragma unroll
        for (int q = 0; q < 3; q++) {
            float4 y = *(const float4*)&Y[row * QS + l8 * 12 + q * 4];
            s += (y.x + y.y) + (y.z + y.w);
            s2 = fmaf(y.x, y.x, fmaf(y.y, y.y, fmaf(y.z, y.z, fmaf(y.w, y.w, s2))));
        }
        #pragma unroll
        for (int o = 4; o > 0; o >>= 1) {
            s  += __shfl_xor_sync(0xffffffffu, s,  o);
            s2 += __shfl_xor_sync(0xffffffffu, s2, o);
        }
        if (l8 == 0) {
            float mean = s * (1.0f / 96.0f);
            float var  = fmaf(-mean, mean, s2 * (1.0f / 96.0f));
            stats[row]      = mean;
            stats[64 + row] = rsqrtf(var + 1e-5f);
        }
    }
    __syncthreads();

    for (int idx = tid; idx < 6144; idx += 512) {
        int t = idx / CH, c = idx - t * CH;
        float yv = (Y[t * QS + c] - stats[t]) * stats[64 + t];
        dst[idx] = fmaf(yv, gam[c], beta[c]);
    }
}

// ---------------------------------------------------------------------------
// Input order (setup_inputs dict order):
//   0: x | 1..7: sa1 | 8..14: sa2 | 15..20: ff1 | 21..26: ff2
// ---------------------------------------------------------------------------
extern "C" void kernel_launch(void* const* d_in, const int* in_sizes, int n_in,
                              void* d_out, int out_size) {
    const float* x = (const float*)d_in[0];
    float *imgA, *imgB;
    cudaGetSymbolAddress((void**)&imgA, g_imgA);
    cudaGetSymbolAddress((void**)&imgB, g_imgB);

    cudaFuncSetAttribute(attn_kernel<0>, cudaFuncAttributeMaxDynamicSharedMemorySize, ATTN_SMEM);
    cudaFuncSetAttribute(attn_kernel<1>, cudaFuncAttributeMaxDynamicSharedMemorySize, ATTN_SMEM);
    cudaFuncSetAttribute(ffn_kernel,     cudaFuncAttributeMaxDynamicSharedMemorySize, FFN_SMEM);

    dim3 tb(32, 8);
    dim3 tg(HW / 32, CH / 32, BATCH);

    transpose_in_kernel<<<tg, tb>>>(x, imgA);

    attn_kernel<0><<<NWIN, 512, ATTN_SMEM>>>(
        imgA, imgB,
        (const float*)d_in[1], (const float*)d_in[2], (const float*)d_in[3],
        (const float*)d_in[4], (const float*)d_in[5], (const float*)d_in[6],
        (const float*)d_in[7]);

    ffn_kernel<<<NWIN, 512, FFN_SMEM>>>(
        imgB, imgA,
        (const float*)d_in[15], (const float*)d_in[16], (const float*)d_in[17],
        (const float*)d_in[18], (const float*)d_in[19], (const float*)d_in[20]);

    attn_kernel<1><<<NWIN, 512, ATTN_SMEM>>>(
        imgA, imgB,
        (const float*)d_in[8], (const float*)d_in[9], (const float*)d_in[10],
        (const float*)d_in[11], (const float*)d_in[12], (const float*)d_in[13],
        (const float*)d_in[14]);

    ffn_kernel<<<NWIN, 512, FFN_SMEM>>>(
        imgB, imgA,
        (const float*)d_in[21], (const float*)d_in[22], (const float*)d_in[23],
        (const float*)d_in[24], (const float*)d_in[25], (const float*)d_in[26]);

    transpose_out_kernel<<<tg, tb>>>(imgA, (float*)d_out);
}

// round 7
// speedup vs baseline: 1.2695x; 1.0508x over previous
#include <cuda_runtime.h>
#include <math.h>
#include <stdint.h>

#define CH    96
#define HH    192
#define WWI   192
#define HW    (HH*WWI)        // 36864
#define BATCH 4
#define NWIN_PER 576          // 24*24 windows per image
#define NWIN  (BATCH*NWIN_PER)
#define NTOK  64
#define NHEAD 6
#define HDIM  16
#define QS    100             // row stride for 64-row fp32 tiles
#define HS    196             // FFN hidden stride

// 56.6 MB each — static device scratch (no allocations allowed)
__device__ float g_imgA[BATCH*HW*CH];
__device__ float g_imgB[BATCH*HW*CH];

// ---------------------------------------------------------------------------
// FMA-only exp. Valid for x <= 0 (softmax-shifted logits); clamps at -80.
// ---------------------------------------------------------------------------
__device__ __forceinline__ float fexp(float x) {
    x = fmaxf(x, -80.0f);
    const float L2E = 1.4426950408889634f;
    float t = fmaf(x, L2E, 12582912.0f);
    float n = t - 12582912.0f;
    float f = fmaf(x, L2E, -n);
    float p = 1.5403530393381608e-4f;
    p = fmaf(p, f, 1.3333558146428443e-3f);
    p = fmaf(p, f, 9.6181291076284772e-3f);
    p = fmaf(p, f, 5.5504108664821580e-2f);
    p = fmaf(p, f, 2.4022650695910072e-1f);
    p = fmaf(p, f, 6.9314718055994531e-1f);
    p = fmaf(p, f, 1.0f);
    int e = (int)n;
    float s = __int_as_float((127 + e) << 23);
    return p * s;
}

// ---------------------------------------------------------------------------
// tf32 MMA helpers (3xTF32 split for near-fp32 accuracy)
// ---------------------------------------------------------------------------
__device__ __forceinline__ uint32_t f2tf(float x) {
    uint32_t r; asm("cvt.rna.tf32.f32 %0, %1;" : "=r"(r) : "f"(x)); return r;
}
__device__ __forceinline__ void tfsplit(float x, uint32_t& h, uint32_t& l) {
    h = f2tf(x);
    l = f2tf(x - __uint_as_float(h));
}
__device__ __forceinline__ void mma_m16n8k8(float4& d,
    uint32_t a0, uint32_t a1, uint32_t a2, uint32_t a3,
    uint32_t b0, uint32_t b1)
{
    asm volatile("mma.sync.aligned.m16n8k8.row.col.f32.tf32.tf32.f32 "
                 "{%0,%1,%2,%3},{%4,%5,%6,%7},{%8,%9},{%0,%1,%2,%3};"
                 : "+f"(d.x), "+f"(d.y), "+f"(d.z), "+f"(d.w)
                 : "r"(a0), "r"(a1), "r"(a2), "r"(a3), "r"(b0), "r"(b1));
}

// C = A(64 x K, smem, row stride lda) @ B(K x N, gmem row-major, stride ldb)
// warp computes one 16-row m-tile x NT 8-col n-tiles. mg=lane>>2, mt=lane&3.
template<int NT, int KSTEPS>
__device__ __forceinline__ void mma_gemm(
    float4* acc, const float* A, int lda, int m0,
    const float* __restrict__ B, int ldb, int n0, int mg, int mt)
{
    #pragma unroll 2
    for (int ks = 0; ks < KSTEPS; ks++) {
        const int k0 = ks * 8;
        uint32_t ah[4], al[4];
        tfsplit(A[(m0 + mg) * lda + k0 + mt],         ah[0], al[0]);
        tfsplit(A[(m0 + mg + 8) * lda + k0 + mt],     ah[1], al[1]);
        tfsplit(A[(m0 + mg) * lda + k0 + mt + 4],     ah[2], al[2]);
        tfsplit(A[(m0 + mg + 8) * lda + k0 + mt + 4], ah[3], al[3]);
        #pragma unroll
        for (int j = 0; j < NT; j++) {
            float w0 = __ldg(&B[(k0 + mt) * ldb + n0 + j * 8 + mg]);
            float w1 = __ldg(&B[(k0 + mt + 4) * ldb + n0 + j * 8 + mg]);
            uint32_t bh0, bl0, bh1, bl1;
            tfsplit(w0, bh0, bl0);
            tfsplit(w1, bh1, bl1);
            mma_m16n8k8(acc[j], ah[0], ah[1], ah[2], ah[3], bh0, bh1);
            mma_m16n8k8(acc[j], ah[0], ah[1], ah[2], ah[3], bl0, bl1);
            mma_m16n8k8(acc[j], al[0], al[1], al[2], al[3], bh0, bh1);
        }
    }
}

// ---------------------------------------------------------------------------
// Transposes: [B,C,H,W] <-> [B,HW,C]
// ---------------------------------------------------------------------------
__global__ void transpose_in_kernel(const float* __restrict__ x, float* __restrict__ img) {
    __shared__ float tile[32][33];
    int b = blockIdx.z;
    int hw0 = blockIdx.x * 32, c0 = blockIdx.y * 32;
    const float* src = x + (size_t)b * CH * HW;
    float* dst = img + (size_t)b * HW * CH;
    #pragma unroll
    for (int i = threadIdx.y; i < 32; i += 8)
        tile[i][threadIdx.x] = src[(size_t)(c0 + i) * HW + hw0 + threadIdx.x];
    __syncthreads();
    #pragma unroll
    for (int i = threadIdx.y; i < 32; i += 8)
        dst[(size_t)(hw0 + i) * CH + c0 + threadIdx.x] = tile[threadIdx.x][i];
}

__global__ void transpose_out_kernel(const float* __restrict__ img, float* __restrict__ x) {
    __shared__ float tile[32][33];
    int b = blockIdx.z;
    int hw0 = blockIdx.x * 32, c0 = blockIdx.y * 32;
    const float* src = img + (size_t)b * HW * CH;
    float* dst = x + (size_t)b * CH * HW;
    #pragma unroll
    for (int i = threadIdx.y; i < 32; i += 8)
        tile[i][threadIdx.x] = src[(size_t)(hw0 + i) * CH + c0 + threadIdx.x];
    __syncthreads();
    #pragma unroll
    for (int i = threadIdx.y; i < 32; i += 8)
        dst[(size_t)(c0 + i) * HW + hw0 + threadIdx.x] = tile[threadIdx.x][i];
}

// ---------------------------------------------------------------------------
// Fused window attention: GEMMs on tensor cores (3xTF32), heads SIMT.
// smem floats: Xs/Qb/Kb/Vb/Ob 5*6400 | S 2*64*68 | Tb 1360 | stats 128 |
//              Cnt 64  = 42,256 floats = 169,024 B
// ---------------------------------------------------------------------------
#define ATTN_SMEM (42256 * 4)

template<int SHIFTED>
__global__ void __launch_bounds__(512, 1) attn_kernel(
    const float* __restrict__ in, float* __restrict__ out,
    const float* __restrict__ wqkv, const float* __restrict__ bqkv,
    const float* __restrict__ table, const float* __restrict__ wproj,
    const float* __restrict__ bproj, const float* __restrict__ gam,
    const float* __restrict__ beta)
{
    extern __shared__ float sm[];
    float* Xs    = sm;                 // 64 x QS
    float* Qb    = Xs + 64*QS;         // 64 x QS (later reused as Y)
    float* Kb    = Qb + 64*QS;
    float* Vb    = Kb + 64*QS;
    float* Ob    = Vb + 64*QS;
    float* S     = Ob + 64*QS;         // 2 x 64 x 68
    float* Tb    = S + 2*64*68;        // 1360 (1350 used)
    float* stats = Tb + 1360;          // 128
    int*   Cnt   = (int*)(stats + 128);// 64

    const int tid = threadIdx.x;
    const int wid = blockIdx.x;
    const int b  = wid / NWIN_PER;
    const int wl = wid - b * NWIN_PER;
    const int wr = wl / 24, wc = wl - (wl / 24) * 24;
    const float* src = in  + (size_t)b * HW * CH;
    float*       dst = out + (size_t)b * HW * CH;

    // ---- gather window tokens + stage table + region ids ----
    for (int idx = tid; idx < NTOK * CH; idx += 512) {
        int t = idx / CH, c = idx - t * CH;
        int r = t >> 3, cl = t & 7;
        int h = wr * 8 + r, w = wc * 8 + cl;
        if (SHIFTED) { h += 4; if (h >= HH) h -= HH; w += 4; if (w >= WWI) w -= WWI; }
        Xs[t * QS + c] = src[(h * WWI + w) * CH + c];
    }
    for (int idx = tid; idx < 1350; idx += 512) Tb[idx] = table[idx];
    if (SHIFTED && tid < 64) {
        int ri = tid >> 3, ci = tid & 7;
        Cnt[tid] = ((wr == 23) ? (ri < 4 ? 1 : 2) : 0) * 3
                 + ((wc == 23) ? (ci < 4 ? 1 : 2) : 0);
    }
    __syncthreads();

    const int wg = tid >> 5, tx = tid & 31;   // 16 warps
    const int mg = tx >> 2, mt = tx & 3;      // mma lane coords
    const int m0 = (wg & 3) * 16;             // m-tile
    const int nch = wg >> 2;                  // n-chunk

    // ---- QKV GEMM: 64x288x96 via mma; warp covers 16 rows x 72 cols ----
    {
        float4 acc[9];
        #pragma unroll
        for (int j = 0; j < 9; j++) {
            int c = nch * 72 + j * 8 + 2 * mt;
            float b0 = __ldg(&bqkv[c]), b1 = __ldg(&bqkv[c + 1]);
            acc[j].x = b0; acc[j].y = b1; acc[j].z = b0; acc[j].w = b1;
        }
        mma_gemm<9, 12>(acc, Xs, QS, m0, wqkv, 288, nch * 72, mg, mt);
        #pragma unroll
        for (int j = 0; j < 9; j++) {
            int c = nch * 72 + j * 8 + 2 * mt;
            int rA = m0 + mg, rB = rA + 8;
            float v[4] = {acc[j].x, acc[j].y, acc[j].z, acc[j].w};
            int   rr[4] = {rA, rA, rB, rB};
            int   cc[4] = {c, c + 1, c, c + 1};
            #pragma unroll
            for (int e = 0; e < 4; e++) {
                int col = cc[e];
                if (col < 96)       Qb[rr[e] * QS + col]         = v[e];
                else if (col < 192) Kb[rr[e] * QS + (col - 96)]  = v[e];
                else                Vb[rr[e] * QS + (col - 192)] = v[e];
            }
        }
    }
    __syncthreads();

    // ---- heads: 2 in flight (warps 0-7 -> head 2it, warps 8-15 -> 2it+1) ----
    const int hg   = wg >> 3;          // head group
    const int rowg = wg & 7;
    const int i0   = rowg * 8;
    int cni[8], cj0 = 0, cj1 = 0;
    if (SHIFTED) {
        cj0 = Cnt[tx]; cj1 = Cnt[tx + 32];
        #pragma unroll
        for (int r = 0; r < 8; r++) cni[r] = Cnt[i0 + r];
    }
    for (int it = 0; it < 3; it++) {
        const int hd = it * 2 + hg;
        float* Sg = S + hg * 64 * 68;

        float sc[8][2];
        #pragma unroll
        for (int r = 0; r < 8; r++) { sc[r][0] = 0.f; sc[r][1] = 0.f; }
        #pragma unroll
        for (int d4 = 0; d4 < 4; d4++) {
            float4 k0 = *(const float4*)&Kb[tx * QS + hd * 16 + d4 * 4];
            float4 k1 = *(const float4*)&Kb[(tx + 32) * QS + hd * 16 + d4 * 4];
            #pragma unroll
            for (int r = 0; r < 8; r++) {
                float4 q = *(const float4*)&Qb[(i0 + r) * QS + hd * 16 + d4 * 4];
                sc[r][0] = fmaf(q.x, k0.x, fmaf(q.y, k0.y, fmaf(q.z, k0.z, fmaf(q.w, k0.w, sc[r][0]))));
                sc[r][1] = fmaf(q.x, k1.x, fmaf(q.y, k1.y, fmaf(q.z, k1.z, fmaf(q.w, k1.w, sc[r][1]))));
            }
        }
        #pragma unroll
        for (int r = 0; r < 8; r++) {
            int i = i0 + r;
            int ri = i >> 3, ci = i & 7;
            float v[2];
            #pragma unroll
            for (int cj = 0; cj < 2; cj++) {
                int j = tx + 32 * cj;
                int rj = j >> 3, cjj = j & 7;
                int ridx = (ri - rj + 7) * 15 + (ci - cjj + 7);
                float bias = Tb[ridx * 6 + hd];
                if (SHIFTED) {
                    int cjv = cj ? cj1 : cj0;
                    if (cni[r] != cjv) bias -= 100.f;
                }
                v[cj] = fmaf(sc[r][cj], 0.25f, bias);
            }
            float mx = fmaxf(v[0], v[1]);
            #pragma unroll
            for (int o = 16; o > 0; o >>= 1) mx = fmaxf(mx, __shfl_xor_sync(0xffffffffu, mx, o));
            float e0 = fexp(v[0] - mx), e1 = fexp(v[1] - mx);
            float ssum = e0 + e1;
            #pragma unroll
            for (int o = 16; o > 0; o >>= 1) ssum += __shfl_xor_sync(0xffffffffu, ssum, o);
            float inv = 1.0f / ssum;
            Sg[i * 68 + tx]      = e0 * inv;
            Sg[i * 68 + tx + 32] = e1 * inv;
        }
        __syncthreads();

        // attn @ V : thread = (row, d4 group) within its head's 256 threads
        {
            int gtid = tid & 255;
            int d4   = gtid & 3;
            int row  = gtid >> 2;
            float4 o = make_float4(0.f, 0.f, 0.f, 0.f);
            #pragma unroll 4
            for (int j4 = 0; j4 < 16; j4++) {
                float4 s4 = *(const float4*)&Sg[row * 68 + j4 * 4];
                #pragma unroll
                for (int jj = 0; jj < 4; jj++) {
                    float sj = (jj == 0) ? s4.x : (jj == 1) ? s4.y : (jj == 2) ? s4.z : s4.w;
                    float4 v4 = *(const float4*)&Vb[(j4 * 4 + jj) * QS + hd * 16 + d4 * 4];
                    o.x = fmaf(sj, v4.x, o.x);
                    o.y = fmaf(sj, v4.y, o.y);
                    o.z = fmaf(sj, v4.z, o.z);
                    o.w = fmaf(sj, v4.w, o.w);
                }
            }
            *(float4*)&Ob[row * QS + hd * 16 + d4 * 4] = o;
        }
        __syncthreads();
    }

    // ---- proj GEMM 64x96x96 via mma + residual ----
    float* Y = Qb;  // reuse
    {
        float4 acc[3];
        #pragma unroll
        for (int j = 0; j < 3; j++) {
            int c = nch * 24 + j * 8 + 2 * mt;
            float b0 = __ldg(&bproj[c]), b1 = __ldg(&bproj[c + 1]);
            acc[j].x = b0; acc[j].y = b1; acc[j].z = b0; acc[j].w = b1;
        }
        mma_gemm<3, 12>(acc, Ob, QS, m0, wproj, 96, nch * 24, mg, mt);
        #pragma unroll
        for (int j = 0; j < 3; j++) {
            int c = nch * 24 + j * 8 + 2 * mt;
            int rA = m0 + mg, rB = rA + 8;
            Y[rA * QS + c]     = acc[j].x + Xs[rA * QS + c];
            Y[rA * QS + c + 1] = acc[j].y + Xs[rA * QS + c + 1];
            Y[rB * QS + c]     = acc[j].z + Xs[rB * QS + c];
            Y[rB * QS + c + 1] = acc[j].w + Xs[rB * QS + c + 1];
        }
    }
    __syncthreads();

    // ---- LayerNorm: 8 threads per row, single pass ----
    {
        int row = tid >> 3, l8 = tid & 7;
        float s = 0.f, s2 = 0.f;
        #pragma unroll
        for (int q = 0; q < 3; q++) {
            float4 y = *(const float4*)&Y[row * QS + l8 * 12 + q * 4];
            s += (y.x + y.y) + (y.z + y.w);
            s2 = fmaf(y.x, y.x, fmaf(y.y, y.y, fmaf(y.z, y.z, fmaf(y.w, y.w, s2))));
        }
        #pragma unroll
        for (int o = 4; o > 0; o >>= 1) {
            s  += __shfl_xor_sync(0xffffffffu, s,  o);
            s2 += __shfl_xor_sync(0xffffffffu, s2, o);
        }
        if (l8 == 0) {
            float mean = s * (1.0f / 96.0f);
            float var  = fmaf(-mean, mean, s2 * (1.0f / 96.0f));
            stats[row]      = mean;
            stats[64 + row] = rsqrtf(var + 1e-5f);
        }
    }
    __syncthreads();

    // ---- scatter (same coords as gather: roll cancels) ----
    for (int idx = tid; idx < NTOK * CH; idx += 512) {
        int t = idx / CH, c = idx - t * CH;
        int r = t >> 3, cl = t & 7;
        int h = wr * 8 + r, w = wc * 8 + cl;
        if (SHIFTED) { h += 4; if (h >= HH) h -= HH; w += 4; if (w >= WWI) w -= WWI; }
        float yv = (Y[t * QS + c] - stats[t]) * stats[64 + t];
        dst[(h * WWI + w) * CH + c] = fmaf(yv, gam[c], beta[c]);
    }
}

// ---------------------------------------------------------------------------
// Fused FFN: both GEMMs on tensor cores (3xTF32), weights LDG-direct.
// smem floats: Xs 64x100 | H1 64x196 | Y 64x100 | stats 128 = 25,472
// ---------------------------------------------------------------------------
#define FFN_SMEM (25472 * 4)

__global__ void __launch_bounds__(512, 1) ffn_kernel(
    const float* __restrict__ in, float* __restrict__ out,
    const float* __restrict__ w1, const float* __restrict__ b1,
    const float* __restrict__ w2, const float* __restrict__ b2,
    const float* __restrict__ gam, const float* __restrict__ beta)
{
    extern __shared__ float sm[];
    float* Xs    = sm;                  // 64 x QS
    float* H1    = Xs + 64*QS;          // 64 x HS
    float* Y     = H1 + 64*HS;          // 64 x QS
    float* stats = Y + 64*QS;

    const int tid = threadIdx.x;
    const size_t t0 = (size_t)blockIdx.x * 64;
    const float* src = in + t0 * CH;
    float*       dst = out + t0 * CH;

    for (int idx = tid; idx < 6144; idx += 512) {
        int t = idx / CH, c = idx - t * CH;
        Xs[t * QS + c] = src[idx];
    }
    __syncthreads();

    const int wg = tid >> 5, tx = tid & 31;
    const int mg = tx >> 2, mt = tx & 3;
    const int m0 = (wg & 3) * 16;
    const int nch = wg >> 2;

    // GEMM1: 64x192x96 + GELU -> H1
    {
        float4 acc[6];
        #pragma unroll
        for (int j = 0; j < 6; j++) {
            int c = nch * 48 + j * 8 + 2 * mt;
            float v0 = __ldg(&b1[c]), v1 = __ldg(&b1[c + 1]);
            acc[j].x = v0; acc[j].y = v1; acc[j].z = v0; acc[j].w = v1;
        }
        mma_gemm<6, 12>(acc, Xs, QS, m0, w1, 192, nch * 48, mg, mt);
        #pragma unroll
        for (int j = 0; j < 6; j++) {
            int c = nch * 48 + j * 8 + 2 * mt;
            int rA = m0 + mg, rB = rA + 8;
            float v[4] = {acc[j].x, acc[j].y, acc[j].z, acc[j].w};
            int   rr[4] = {rA, rA, rB, rB};
            int   cc[4] = {c, c + 1, c, c + 1};
            #pragma unroll
            for (int e = 0; e < 4; e++) {
                float x = v[e];
                H1[rr[e] * HS + cc[e]] = 0.5f * x * (1.0f + erff(x * 0.70710678118654752f));
            }
        }
    }
    __syncthreads();

    // GEMM2: 64x96x192 + residual -> Y
    {
        float4 acc[3];
        #pragma unroll
        for (int j = 0; j < 3; j++) {
            int c = nch * 24 + j * 8 + 2 * mt;
            float v0 = __ldg(&b2[c]), v1 = __ldg(&b2[c + 1]);
            acc[j].x = v0; acc[j].y = v1; acc[j].z = v0; acc[j].w = v1;
        }
        mma_gemm<3, 24>(acc, H1, HS, m0, w2, 96, nch * 24, mg, mt);
        #pragma unroll
        for (int j = 0; j < 3; j++) {
            int c = nch * 24 + j * 8 + 2 * mt;
            int rA = m0 + mg, rB = rA + 8;
            Y[rA * QS + c]     = acc[j].x + Xs[rA * QS + c];
            Y[rA * QS + c + 1] = acc[j].y + Xs[rA * QS + c + 1];
            Y[rB * QS + c]     = acc[j].z + Xs[rB * QS + c];
            Y[rB * QS + c + 1] = acc[j].w + Xs[rB * QS + c + 1];
        }
    }
    __syncthreads();

    // LayerNorm: 8 threads per row, single pass
    {
        int row = tid >> 3, l8 = tid & 7;
        float s = 0.f, s2 = 0.f;
        #pragma unroll
        for (int q = 0; q < 3; q++) {
            float4 y = *(const float4*)&Y[row * QS + l8 * 12 + q * 4];
            s += (y.x + y.y) + (y.z + y.w);
            s2 = fmaf(y.x, y.x, fmaf(y.y, y.y, fmaf(y.z, y.z, fmaf(y.w, y.w, s2))));
        }
        #pragma unroll
        for (int o = 4; o > 0; o >>= 1) {
            s  += __shfl_xor_sync(0xffffffffu, s,  o);
            s2 += __shfl_xor_sync(0xffffffffu, s2, o);
        }
        if (l8 == 0) {
            float mean = s * (1.0f / 96.0f);
            float var  = fmaf(-mean, mean, s2 * (1.0f / 96.0f));
            stats[row]      = mean;
            stats[64 + row] = rsqrtf(var + 1e-5f);
        }
    }
    __syncthreads();

    for (int idx = tid; idx < 6144; idx += 512) {
        int t = idx / CH, c = idx - t * CH;
        float yv = (Y[t * QS + c] - stats[t]) * stats[64 + t];
        dst[idx] = fmaf(yv, gam[c], beta[c]);
    }
}

// ---------------------------------------------------------------------------
// Input order (setup_inputs dict order):
//   0: x | 1..7: sa1 | 8..14: sa2 | 15..20: ff1 | 21..26: ff2
// ---------------------------------------------------------------------------
extern "C" void kernel_launch(void* const* d_in, const int* in_sizes, int n_in,
                              void* d_out, int out_size) {
    const float* x = (const float*)d_in[0];
    float *imgA, *imgB;
    cudaGetSymbolAddress((void**)&imgA, g_imgA);
    cudaGetSymbolAddress((void**)&imgB, g_imgB);

    cudaFuncSetAttribute(attn_kernel<0>, cudaFuncAttributeMaxDynamicSharedMemorySize, ATTN_SMEM);
    cudaFuncSetAttribute(attn_kernel<1>, cudaFuncAttributeMaxDynamicSharedMemorySize, ATTN_SMEM);
    cudaFuncSetAttribute(ffn_kernel,     cudaFuncAttributeMaxDynamicSharedMemorySize, FFN_SMEM);

    dim3 tb(32, 8);
    dim3 tg(HW / 32, CH / 32, BATCH);

    transpose_in_kernel<<<tg, tb>>>(x, imgA);

    attn_kernel<0><<<NWIN, 512, ATTN_SMEM>>>(
        imgA, imgB,
        (const float*)d_in[1], (const float*)d_in[2], (const float*)d_in[3],
        (const float*)d_in[4], (const float*)d_in[5], (const float*)d_in[6],
        (const float*)d_in[7]);

    ffn_kernel<<<NWIN, 512, FFN_SMEM>>>(
        imgB, imgA,
        (const float*)d_in[15], (const float*)d_in[16], (const float*)d_in[17],
        (const float*)d_in[18], (const float*)d_in[19], (const float*)d_in[20]);

    attn_kernel<1><<<NWIN, 512, ATTN_SMEM>>>(
        imgA, imgB,
        (const float*)d_in[8], (const float*)d_in[9], (const float*)d_in[10],
        (const float*)d_in[11], (const float*)d_in[12], (const float*)d_in[13],
        (const float*)d_in[14]);

    ffn_kernel<<<NWIN, 512, FFN_SMEM>>>(
        imgB, imgA,
        (const float*)d_in[21], (const float*)d_in[22], (const float*)d_in[23],
        (const float*)d_in[24], (const float*)d_in[25], (const float*)d_in[26]);

    transpose_out_kernel<<<tg, tb>>>(imgA, (float*)d_out);
}